// round 1
// baseline (speedup 1.0000x reference)
#include <cuda_runtime.h>
#include <math.h>

// Problem constants
constexpr int B_   = 2;
constexpr int S_   = 2048;
constexpr int DIM_ = 1024;
constexpr int NH_  = 16;   // query heads
constexpr int NKV_ = 4;    // kv heads
constexpr int HD_  = 64;   // head dim
constexpr int M_   = B_ * S_;          // 4096 rows
constexpr int NQKV = NH_*HD_ + 2*NKV_*HD_;  // 1536
constexpr float SCALE_ = 0.125f;       // 1/sqrt(64)

// Scratch (device globals: allocation-free)
__device__ float g_Q[M_ * NH_ * HD_];   // 4096 x 1024
__device__ float g_K[M_ * NKV_ * HD_];  // 4096 x 256
__device__ float g_V[M_ * NKV_ * HD_];  // 4096 x 256
__device__ float g_O[M_ * NH_ * HD_];   // 4096 x 1024

// ---------------------------------------------------------------------------
// Kernel 1: fused QKV projection + RoPE epilogue.
// GEMM: X(4096x1024) @ [wq|wk|wv](1024x1536). Tiles 64x64, BK=16, 256 thr,
// each thread 4x4. Column-region is uniform per block (boundaries are
// multiples of 64). RoPE applied to q and k regions in epilogue: within a
// thread's 4 adjacent columns, (c0,c1) and (c2,c3) are rope pairs.
// ---------------------------------------------------------------------------
__global__ __launch_bounds__(256) void qkv_rope_kernel(
    const float* __restrict__ x,
    const float* __restrict__ wq,
    const float* __restrict__ wk,
    const float* __restrict__ wv,
    const float* __restrict__ cosT,   // (2048, 32)
    const float* __restrict__ sinT)   // (2048, 32)
{
    __shared__ float As[16][64 + 1];  // [k][m]
    __shared__ float Bs[16][64 + 1];  // [k][n]

    const int m0 = blockIdx.y * 64;
    const int n0 = blockIdx.x * 64;
    const int tid = threadIdx.x;
    const int tx = tid & 15;
    const int ty = tid >> 4;

    // weight region for this block (uniform)
    const float* w; int ldw, coff;
    if (n0 < 1024)      { w = wq; ldw = 1024; coff = n0; }
    else if (n0 < 1280) { w = wk; ldw = 256;  coff = n0 - 1024; }
    else                { w = wv; ldw = 256;  coff = n0 - 1280; }

    float acc[4][4] = {};

    for (int k0 = 0; k0 < DIM_; k0 += 16) {
        // Load A tile (64 rows x 16 k), coalesced along k
        #pragma unroll
        for (int p = 0; p < 4; p++) {
            int m = (tid >> 4) + p * 16;
            int k = tid & 15;
            As[k][m] = x[(m0 + m) * DIM_ + k0 + k];
        }
        // Load B tile (16 k x 64 n), coalesced along n
        #pragma unroll
        for (int p = 0; p < 4; p++) {
            int n = tid & 63;
            int k = (tid >> 6) + p * 4;
            Bs[k][n] = w[(k0 + k) * ldw + coff + n];
        }
        __syncthreads();

        #pragma unroll
        for (int kk = 0; kk < 16; kk++) {
            float a[4], b[4];
            #pragma unroll
            for (int i = 0; i < 4; i++) a[i] = As[kk][ty * 4 + i];
            #pragma unroll
            for (int j = 0; j < 4; j++) b[j] = Bs[kk][tx * 4 + j];
            #pragma unroll
            for (int i = 0; i < 4; i++)
                #pragma unroll
                for (int j = 0; j < 4; j++)
                    acc[i][j] += a[i] * b[j];
        }
        __syncthreads();
    }

    const bool isq = (n0 < 1024);
    const bool isk = (n0 >= 1024 && n0 < 1280);

    #pragma unroll
    for (int i = 0; i < 4; i++) {
        const int row = m0 + ty * 4 + i;
        const int s   = row & (S_ - 1);
        #pragma unroll
        for (int jp = 0; jp < 2; jp++) {
            const int n = n0 + tx * 4 + jp * 2;   // even column of the pair
            float e = acc[i][jp * 2 + 0];
            float o = acc[i][jp * 2 + 1];
            if (isq || isk) {
                const int d = n & 63;             // even dim within head
                const float c  = cosT[s * 32 + (d >> 1)];
                const float sn = sinT[s * 32 + (d >> 1)];
                const float re = e * c - o * sn;
                const float im = e * sn + o * c;
                e = re; o = im;
            }
            if (isq) {
                g_Q[row * 1024 + n + 0] = e;
                g_Q[row * 1024 + n + 1] = o;
            } else if (isk) {
                g_K[row * 256 + (n - 1024) + 0] = e;
                g_K[row * 256 + (n - 1024) + 1] = o;
            } else {
                g_V[row * 256 + (n - 1280) + 0] = e;
                g_V[row * 256 + (n - 1280) + 1] = o;
            }
        }
    }
}

// ---------------------------------------------------------------------------
// Kernel 2: flash attention (fp32), causal. One CTA per (qtile, head, batch).
// 64-query tile, streams 64-key tiles with online softmax. 256 threads,
// each computes a 4x4 microtile of both the score tile and the output tile.
// Dynamic smem: sQt/sKt/sV/sP each [64][65] floats = 66560 B.
// ---------------------------------------------------------------------------
__global__ __launch_bounds__(256) void flash_attn_kernel()
{
    extern __shared__ float sm[];
    float* sQt = sm;                  // [k=dim][r]  stride 65
    float* sKt = sm + 64 * 65;        // [k=dim][c]  stride 65
    float* sV  = sm + 2 * 64 * 65;    // [kv][c=dim] stride 65
    float* sP  = sm + 3 * 64 * 65;    // [r][kv]     stride 65

    const int qi = blockIdx.x;        // 0..31
    const int h  = blockIdx.y;        // 0..15
    const int b  = blockIdx.z;        // 0..1
    const int g  = h >> 2;            // kv group
    const int q0 = qi * 64;

    const int tid = threadIdx.x;
    const int tx = tid & 15;
    const int ty = tid >> 4;

    // Load Q tile transposed: sQt[d][r]
    for (int idx = tid; idx < 4096; idx += 256) {
        const int r = idx >> 6;
        const int d = idx & 63;
        sQt[d * 65 + r] = g_Q[(b * S_ + q0 + r) * 1024 + h * 64 + d];
    }

    float m_i[4], l_i[4], acc[4][4] = {};
    #pragma unroll
    for (int i = 0; i < 4; i++) { m_i[i] = -INFINITY; l_i[i] = 0.0f; }

    for (int t = 0; t <= qi; t++) {
        const int kv0 = t * 64;
        __syncthreads();   // previous PV done before overwriting K/V

        // Load K tile transposed: sKt[d][c]
        for (int idx = tid; idx < 4096; idx += 256) {
            const int c = idx >> 6;
            const int d = idx & 63;
            sKt[d * 65 + c] = g_K[(b * S_ + kv0 + c) * 256 + g * 64 + d];
        }
        // Load V tile natural: sV[k][c]
        for (int idx = tid; idx < 4096; idx += 256) {
            const int k = idx >> 6;
            const int c = idx & 63;
            sV[k * 65 + c] = g_V[(b * S_ + kv0 + k) * 256 + g * 64 + c];
        }
        __syncthreads();

        // S = Q K^T * scale
        float sc[4][4] = {};
        #pragma unroll 8
        for (int kk = 0; kk < 64; kk++) {
            float a[4], bb[4];
            #pragma unroll
            for (int i = 0; i < 4; i++) a[i] = sQt[kk * 65 + ty * 4 + i];
            #pragma unroll
            for (int j = 0; j < 4; j++) bb[j] = sKt[kk * 65 + tx * 4 + j];
            #pragma unroll
            for (int i = 0; i < 4; i++)
                #pragma unroll
                for (int j = 0; j < 4; j++)
                    sc[i][j] += a[i] * bb[j];
        }

        const bool diag = (t == qi);
        #pragma unroll
        for (int i = 0; i < 4; i++) {
            const int rl = ty * 4 + i;
            float p[4];
            float mloc = -INFINITY;
            #pragma unroll
            for (int j = 0; j < 4; j++) {
                float v = sc[i][j] * SCALE_;
                if (diag && (tx * 4 + j > rl)) v = -INFINITY;
                p[j] = v;
                mloc = fmaxf(mloc, v);
            }
            // row max across the 16 threads sharing this row
            #pragma unroll
            for (int off = 8; off >= 1; off >>= 1)
                mloc = fmaxf(mloc, __shfl_xor_sync(0xffffffffu, mloc, off));

            const float m_new = fmaxf(m_i[i], mloc);
            const float f = __expf(m_i[i] - m_new);
            float lsum = 0.0f;
            #pragma unroll
            for (int j = 0; j < 4; j++) {
                const float e = __expf(p[j] - m_new);
                sP[rl * 65 + tx * 4 + j] = e;
                lsum += e;
            }
            #pragma unroll
            for (int off = 8; off >= 1; off >>= 1)
                lsum += __shfl_xor_sync(0xffffffffu, lsum, off);

            l_i[i] = l_i[i] * f + lsum;
            m_i[i] = m_new;
            #pragma unroll
            for (int j = 0; j < 4; j++) acc[i][j] *= f;
        }
        __syncthreads();

        // O += P @ V
        #pragma unroll 8
        for (int kk = 0; kk < 64; kk++) {
            float a[4], bb[4];
            #pragma unroll
            for (int i = 0; i < 4; i++) a[i] = sP[(ty * 4 + i) * 65 + kk];
            #pragma unroll
            for (int j = 0; j < 4; j++) bb[j] = sV[kk * 65 + tx * 4 + j];
            #pragma unroll
            for (int i = 0; i < 4; i++)
                #pragma unroll
                for (int j = 0; j < 4; j++)
                    acc[i][j] += a[i] * bb[j];
        }
    }

    // Normalize and write O
    #pragma unroll
    for (int i = 0; i < 4; i++) {
        const float inv_l = 1.0f / l_i[i];
        const int row = b * S_ + q0 + ty * 4 + i;
        #pragma unroll
        for (int j = 0; j < 4; j++)
            g_O[row * 1024 + h * 64 + tx * 4 + j] = acc[i][j] * inv_l;
    }
}

// ---------------------------------------------------------------------------
// Kernel 3: output projection. g_O(4096x1024) @ wo(1024x1024) -> d_out.
// ---------------------------------------------------------------------------
__global__ __launch_bounds__(256) void out_gemm_kernel(
    const float* __restrict__ wo, float* __restrict__ out)
{
    __shared__ float As[16][64 + 1];
    __shared__ float Bs[16][64 + 1];

    const int m0 = blockIdx.y * 64;
    const int n0 = blockIdx.x * 64;
    const int tid = threadIdx.x;
    const int tx = tid & 15;
    const int ty = tid >> 4;

    float acc[4][4] = {};

    for (int k0 = 0; k0 < 1024; k0 += 16) {
        #pragma unroll
        for (int p = 0; p < 4; p++) {
            int m = (tid >> 4) + p * 16;
            int k = tid & 15;
            As[k][m] = g_O[(m0 + m) * 1024 + k0 + k];
        }
        #pragma unroll
        for (int p = 0; p < 4; p++) {
            int n = tid & 63;
            int k = (tid >> 6) + p * 4;
            Bs[k][n] = wo[(k0 + k) * 1024 + n0 + n];
        }
        __syncthreads();

        #pragma unroll
        for (int kk = 0; kk < 16; kk++) {
            float a[4], b[4];
            #pragma unroll
            for (int i = 0; i < 4; i++) a[i] = As[kk][ty * 4 + i];
            #pragma unroll
            for (int j = 0; j < 4; j++) b[j] = Bs[kk][tx * 4 + j];
            #pragma unroll
            for (int i = 0; i < 4; i++)
                #pragma unroll
                for (int j = 0; j < 4; j++)
                    acc[i][j] += a[i] * b[j];
        }
        __syncthreads();
    }

    #pragma unroll
    for (int i = 0; i < 4; i++)
        #pragma unroll
        for (int j = 0; j < 4; j++)
            out[(m0 + ty * 4 + i) * 1024 + n0 + tx * 4 + j] = acc[i][j];
}

// ---------------------------------------------------------------------------
// Launch
// inputs: 0=x 1=cos 2=sin 3=mask(unused) 4=wq 5=wk 6=wv 7=wo
// ---------------------------------------------------------------------------
extern "C" void kernel_launch(void* const* d_in, const int* in_sizes, int n_in,
                              void* d_out, int out_size)
{
    const float* x    = (const float*)d_in[0];
    const float* cosT = (const float*)d_in[1];
    const float* sinT = (const float*)d_in[2];
    const float* wq   = (const float*)d_in[4];
    const float* wk   = (const float*)d_in[5];
    const float* wv   = (const float*)d_in[6];
    const float* wo   = (const float*)d_in[7];
    float* out = (float*)d_out;

    constexpr int FLASH_SMEM = 4 * 64 * 65 * 4;  // 66560 B
    cudaFuncSetAttribute(flash_attn_kernel,
                         cudaFuncAttributeMaxDynamicSharedMemorySize, FLASH_SMEM);

    // K1: QKV + RoPE. Grid: 1536/64 = 24 col tiles, 4096/64 = 64 row tiles.
    qkv_rope_kernel<<<dim3(24, 64), 256>>>(x, wq, wk, wv, cosT, sinT);

    // K2: flash attention. Grid: (32 qtiles, 16 heads, 2 batch).
    flash_attn_kernel<<<dim3(32, 16, 2), 256, FLASH_SMEM>>>();

    // K3: output projection. Grid: 1024/64 = 16 col tiles, 64 row tiles.
    out_gemm_kernel<<<dim3(16, 64), 256>>>(wo, out);
}

// round 2
// speedup vs baseline: 1.2505x; 1.2505x over previous
#include <cuda_runtime.h>
#include <math.h>

constexpr int B_   = 2;
constexpr int S_   = 2048;
constexpr int DIM_ = 1024;
constexpr int NH_  = 16;
constexpr int NKV_ = 4;
constexpr int HD_  = 64;
constexpr int M_   = B_ * S_;     // 4096
constexpr float SCALE_ = 0.125f;  // 1/sqrt(64)

// Scratch (device globals: allocation-free)
__device__ float g_Q[M_ * NH_ * HD_];   // 4096 x 1024 (rope'd)
__device__ float g_K[M_ * NKV_ * HD_];  // 4096 x 256  (rope'd)
__device__ float g_V[M_ * NKV_ * HD_];  // 4096 x 256
__device__ float g_O[M_ * NH_ * HD_];   // 4096 x 1024

// ---------------------------------------------------------------------------
// Kernel 1: fused QKV projection + RoPE epilogue.
// X(4096x1024) @ [wq|wk|wv](1024x1536). 128x128 tile, BK=16, 256 threads,
// 8x8 microtile, float4 fragments.
// ---------------------------------------------------------------------------
__global__ __launch_bounds__(256) void qkv_rope_kernel(
    const float* __restrict__ x,
    const float* __restrict__ wq,
    const float* __restrict__ wk,
    const float* __restrict__ wv,
    const float* __restrict__ cosT,   // (2048, 32)
    const float* __restrict__ sinT)
{
    __shared__ float As[16][132];  // [k][m]
    __shared__ float Bs[16][132];  // [k][n]

    const int m0 = blockIdx.y * 128;
    const int n0 = blockIdx.x * 128;
    const int tid = threadIdx.x;
    const int tx = tid & 15;
    const int ty = tid >> 4;

    const float* w; int ldw, coff;
    if (n0 < 1024)      { w = wq; ldw = 1024; coff = n0; }
    else if (n0 < 1280) { w = wk; ldw = 256;  coff = n0 - 1024; }
    else                { w = wv; ldw = 256;  coff = n0 - 1280; }

    float acc[8][8] = {};

    const int arow = tid >> 2;        // 0..63
    const int akq  = (tid & 3) * 4;   // 0,4,8,12
    const int bk   = tid >> 5;        // 0..7
    const int bn   = (tid & 31) * 4;  // 0..124

    for (int k0 = 0; k0 < DIM_; k0 += 16) {
        #pragma unroll
        for (int p = 0; p < 2; p++) {
            const int row = arow + p * 64;
            float4 av = *(const float4*)&x[(m0 + row) * DIM_ + k0 + akq];
            As[akq + 0][row] = av.x;
            As[akq + 1][row] = av.y;
            As[akq + 2][row] = av.z;
            As[akq + 3][row] = av.w;
        }
        #pragma unroll
        for (int p = 0; p < 2; p++) {
            const int kb = bk + p * 8;
            *(float4*)&Bs[kb][bn] = *(const float4*)&w[(k0 + kb) * ldw + coff + bn];
        }
        __syncthreads();

        #pragma unroll
        for (int kk = 0; kk < 16; kk++) {
            float4 a0 = *(const float4*)&As[kk][ty * 8];
            float4 a1 = *(const float4*)&As[kk][ty * 8 + 4];
            float4 b0 = *(const float4*)&Bs[kk][tx * 8];
            float4 b1 = *(const float4*)&Bs[kk][tx * 8 + 4];
            float a[8] = {a0.x,a0.y,a0.z,a0.w,a1.x,a1.y,a1.z,a1.w};
            float b[8] = {b0.x,b0.y,b0.z,b0.w,b1.x,b1.y,b1.z,b1.w};
            #pragma unroll
            for (int i = 0; i < 8; i++)
                #pragma unroll
                for (int j = 0; j < 8; j++)
                    acc[i][j] += a[i] * b[j];
        }
        __syncthreads();
    }

    const bool isq = (n0 < 1024);
    const bool isk = (n0 >= 1024 && n0 < 1280);
    const int ncol = n0 + tx * 8;

    #pragma unroll
    for (int i = 0; i < 8; i++) {
        const int row = m0 + ty * 8 + i;
        const int s   = row & (S_ - 1);
        float v[8];
        #pragma unroll
        for (int j = 0; j < 8; j++) v[j] = acc[i][j];
        if (isq || isk) {
            #pragma unroll
            for (int p = 0; p < 4; p++) {
                const int d = (ncol + 2 * p) & 63;   // even dim within head
                const float c  = cosT[s * 32 + (d >> 1)];
                const float sn = sinT[s * 32 + (d >> 1)];
                const float e = v[2 * p], o = v[2 * p + 1];
                v[2 * p]     = e * c - o * sn;
                v[2 * p + 1] = e * sn + o * c;
            }
        }
        float4 lo = make_float4(v[0], v[1], v[2], v[3]);
        float4 hi = make_float4(v[4], v[5], v[6], v[7]);
        if (isq) {
            *(float4*)&g_Q[row * 1024 + ncol]     = lo;
            *(float4*)&g_Q[row * 1024 + ncol + 4] = hi;
        } else if (isk) {
            *(float4*)&g_K[row * 256 + (ncol - 1024)]     = lo;
            *(float4*)&g_K[row * 256 + (ncol - 1024) + 4] = hi;
        } else {
            *(float4*)&g_V[row * 256 + (ncol - 1280)]     = lo;
            *(float4*)&g_V[row * 256 + (ncol - 1280) + 4] = hi;
        }
    }
}

// ---------------------------------------------------------------------------
// Kernel 2: flash attention (fp32), causal. 128-query x 64-key tiles.
// 256 threads, 8x4 microtiles, float4 fragments, P stored transposed.
// ---------------------------------------------------------------------------
__global__ __launch_bounds__(256) void flash_attn_kernel()
{
    extern __shared__ float sm[];
    float* sQt = sm;                   // [d 64][q 128] stride 132
    float* sPt = sm + 64 * 132;        // [kv 64][q 128] stride 132
    float* sKt = sm + 2 * 64 * 132;    // [d 64][k 64]  stride 68
    float* sV  = sm + 2 * 64 * 132 + 64 * 68; // [kv 64][d 64] stride 68

    const int qi = blockIdx.x;        // 0..15  (128-query tiles)
    const int h  = blockIdx.y;
    const int b  = blockIdx.z;
    const int g  = h >> 2;
    const int q0 = qi * 128;

    const int tid = threadIdx.x;
    const int tx = tid & 15;
    const int ty = tid >> 4;

    // Load Q tile transposed (float4 global reads, scalar smem writes)
    #pragma unroll
    for (int it = 0; it < 8; it++) {
        const int idx = tid + it * 256;       // 2048 float4
        const int r  = idx >> 4;
        const int d4 = (idx & 15) * 4;
        float4 qv = *(const float4*)&g_Q[(b * S_ + q0 + r) * 1024 + h * 64 + d4];
        sQt[(d4 + 0) * 132 + r] = qv.x;
        sQt[(d4 + 1) * 132 + r] = qv.y;
        sQt[(d4 + 2) * 132 + r] = qv.z;
        sQt[(d4 + 3) * 132 + r] = qv.w;
    }

    float m_i[8], l_i[8], acc[8][4] = {};
    #pragma unroll
    for (int i = 0; i < 8; i++) { m_i[i] = -INFINITY; l_i[i] = 0.0f; }

    const int ntiles = 2 * qi + 2;   // kv tiles 0 .. 2qi+1

    for (int t = 0; t < ntiles; t++) {
        const int kv0 = t * 64;
        __syncthreads();   // protect K/V/P from previous iteration

        // K tile transposed: sKt[d][c]
        #pragma unroll
        for (int it = 0; it < 4; it++) {
            const int idx = tid + it * 256;   // 1024 float4
            const int c  = idx >> 4;
            const int d4 = (idx & 15) * 4;
            float4 kv = *(const float4*)&g_K[(b * S_ + kv0 + c) * 256 + g * 64 + d4];
            sKt[(d4 + 0) * 68 + c] = kv.x;
            sKt[(d4 + 1) * 68 + c] = kv.y;
            sKt[(d4 + 2) * 68 + c] = kv.z;
            sKt[(d4 + 3) * 68 + c] = kv.w;
        }
        // V tile natural: sV[kv][d]
        #pragma unroll
        for (int it = 0; it < 4; it++) {
            const int idx = tid + it * 256;
            const int k  = idx >> 4;
            const int d4 = (idx & 15) * 4;
            *(float4*)&sV[k * 68 + d4] =
                *(const float4*)&g_V[(b * S_ + kv0 + k) * 256 + g * 64 + d4];
        }
        __syncthreads();

        // S = Q K^T
        float sc[8][4] = {};
        #pragma unroll 4
        for (int kk = 0; kk < 64; kk++) {
            float4 a0 = *(const float4*)&sQt[kk * 132 + ty * 8];
            float4 a1 = *(const float4*)&sQt[kk * 132 + ty * 8 + 4];
            float4 bv = *(const float4*)&sKt[kk * 68 + tx * 4];
            float a[8] = {a0.x,a0.y,a0.z,a0.w,a1.x,a1.y,a1.z,a1.w};
            float bb[4] = {bv.x,bv.y,bv.z,bv.w};
            #pragma unroll
            for (int i = 0; i < 8; i++)
                #pragma unroll
                for (int j = 0; j < 4; j++)
                    sc[i][j] += a[i] * bb[j];
        }

        const bool maskTile = (kv0 + 63 > q0);  // last two tiles need masking
        #pragma unroll
        for (int i = 0; i < 8; i++) {
            const int rl = ty * 8 + i;          // local q row
            float p[4];
            float mloc = -INFINITY;
            #pragma unroll
            for (int j = 0; j < 4; j++) {
                float v = sc[i][j] * SCALE_;
                if (maskTile && (kv0 + tx * 4 + j > q0 + rl)) v = -INFINITY;
                p[j] = v;
                mloc = fmaxf(mloc, v);
            }
            #pragma unroll
            for (int off = 8; off >= 1; off >>= 1)
                mloc = fmaxf(mloc, __shfl_xor_sync(0xffffffffu, mloc, off));

            const float m_new = fmaxf(m_i[i], mloc);
            const float f = __expf(m_i[i] - m_new);
            float lsum = 0.0f;
            #pragma unroll
            for (int j = 0; j < 4; j++) {
                const float e = __expf(p[j] - m_new);
                sPt[(tx * 4 + j) * 132 + rl] = e;   // transposed P
                lsum += e;
            }
            #pragma unroll
            for (int off = 8; off >= 1; off >>= 1)
                lsum += __shfl_xor_sync(0xffffffffu, lsum, off);

            l_i[i] = l_i[i] * f + lsum;
            m_i[i] = m_new;
            #pragma unroll
            for (int j = 0; j < 4; j++) acc[i][j] *= f;
        }
        __syncthreads();   // sPt fully written before PV

        // O += P @ V
        #pragma unroll 4
        for (int kk = 0; kk < 64; kk++) {
            float4 a0 = *(const float4*)&sPt[kk * 132 + ty * 8];
            float4 a1 = *(const float4*)&sPt[kk * 132 + ty * 8 + 4];
            float4 bv = *(const float4*)&sV[kk * 68 + tx * 4];
            float a[8] = {a0.x,a0.y,a0.z,a0.w,a1.x,a1.y,a1.z,a1.w};
            float bb[4] = {bv.x,bv.y,bv.z,bv.w};
            #pragma unroll
            for (int i = 0; i < 8; i++)
                #pragma unroll
                for (int j = 0; j < 4; j++)
                    acc[i][j] += a[i] * bb[j];
        }
    }

    // Normalize and write O
    #pragma unroll
    for (int i = 0; i < 8; i++) {
        const float inv_l = 1.0f / l_i[i];
        const int row = b * S_ + q0 + ty * 8 + i;
        float4 ov = make_float4(acc[i][0] * inv_l, acc[i][1] * inv_l,
                                acc[i][2] * inv_l, acc[i][3] * inv_l);
        *(float4*)&g_O[row * 1024 + h * 64 + tx * 4] = ov;
    }
}

// ---------------------------------------------------------------------------
// Kernel 3: output projection. g_O(4096x1024) @ wo(1024x1024) -> d_out.
// Same 128x128 / 8x8 / float4 structure.
// ---------------------------------------------------------------------------
__global__ __launch_bounds__(256) void out_gemm_kernel(
    const float* __restrict__ wo, float* __restrict__ out)
{
    __shared__ float As[16][132];
    __shared__ float Bs[16][132];

    const int m0 = blockIdx.y * 128;
    const int n0 = blockIdx.x * 128;
    const int tid = threadIdx.x;
    const int tx = tid & 15;
    const int ty = tid >> 4;

    float acc[8][8] = {};

    const int arow = tid >> 2;
    const int akq  = (tid & 3) * 4;
    const int bk   = tid >> 5;
    const int bn   = (tid & 31) * 4;

    for (int k0 = 0; k0 < 1024; k0 += 16) {
        #pragma unroll
        for (int p = 0; p < 2; p++) {
            const int row = arow + p * 64;
            float4 av = *(const float4*)&g_O[(m0 + row) * 1024 + k0 + akq];
            As[akq + 0][row] = av.x;
            As[akq + 1][row] = av.y;
            As[akq + 2][row] = av.z;
            As[akq + 3][row] = av.w;
        }
        #pragma unroll
        for (int p = 0; p < 2; p++) {
            const int kb = bk + p * 8;
            *(float4*)&Bs[kb][bn] = *(const float4*)&wo[(k0 + kb) * 1024 + n0 + bn];
        }
        __syncthreads();

        #pragma unroll
        for (int kk = 0; kk < 16; kk++) {
            float4 a0 = *(const float4*)&As[kk][ty * 8];
            float4 a1 = *(const float4*)&As[kk][ty * 8 + 4];
            float4 b0 = *(const float4*)&Bs[kk][tx * 8];
            float4 b1 = *(const float4*)&Bs[kk][tx * 8 + 4];
            float a[8] = {a0.x,a0.y,a0.z,a0.w,a1.x,a1.y,a1.z,a1.w};
            float b[8] = {b0.x,b0.y,b0.z,b0.w,b1.x,b1.y,b1.z,b1.w};
            #pragma unroll
            for (int i = 0; i < 8; i++)
                #pragma unroll
                for (int j = 0; j < 8; j++)
                    acc[i][j] += a[i] * b[j];
        }
        __syncthreads();
    }

    #pragma unroll
    for (int i = 0; i < 8; i++) {
        const int row = m0 + ty * 8 + i;
        *(float4*)&out[row * 1024 + n0 + tx * 8] =
            make_float4(acc[i][0], acc[i][1], acc[i][2], acc[i][3]);
        *(float4*)&out[row * 1024 + n0 + tx * 8 + 4] =
            make_float4(acc[i][4], acc[i][5], acc[i][6], acc[i][7]);
    }
}

// ---------------------------------------------------------------------------
// inputs: 0=x 1=cos 2=sin 3=mask(unused) 4=wq 5=wk 6=wv 7=wo
// ---------------------------------------------------------------------------
extern "C" void kernel_launch(void* const* d_in, const int* in_sizes, int n_in,
                              void* d_out, int out_size)
{
    const float* x    = (const float*)d_in[0];
    const float* cosT = (const float*)d_in[1];
    const float* sinT = (const float*)d_in[2];
    const float* wq   = (const float*)d_in[4];
    const float* wk   = (const float*)d_in[5];
    const float* wv   = (const float*)d_in[6];
    const float* wo   = (const float*)d_in[7];
    float* out = (float*)d_out;

    constexpr int FLASH_SMEM = (2 * 64 * 132 + 2 * 64 * 68) * 4;  // 102400 B
    cudaFuncSetAttribute(flash_attn_kernel,
                         cudaFuncAttributeMaxDynamicSharedMemorySize, FLASH_SMEM);

    // K1: QKV + RoPE. 1536/128 = 12 col tiles, 4096/128 = 32 row tiles.
    qkv_rope_kernel<<<dim3(12, 32), 256>>>(x, wq, wk, wv, cosT, sinT);

    // K2: flash attention. (16 qtiles, 16 heads, 2 batch).
    flash_attn_kernel<<<dim3(16, 16, 2), 256, FLASH_SMEM>>>();

    // K3: output projection. 1024/128 = 8 col tiles, 32 row tiles.
    out_gemm_kernel<<<dim3(8, 32), 256>>>(wo, out);
}